// round 9
// baseline (speedup 1.0000x reference)
#include <cuda_runtime.h>
#include <cuda_bf16.h>
#include <math.h>

// ---------------- problem constants ----------------
#define NIMG 4
#define BATCH 8
#define SEQ 576
#define DIM 256
#define NHEAD 8
#define DHEAD 32
#define NLAYER 6
#define MLPDIM 512
#define NB (NIMG*BATCH)      // 32
#define TOK (NB*SEQ)         // 18432
#define KPATCH 768           // 3*16*16
#define GRID24 24

// ---------------- scratch (device globals; no allocation allowed) ----------------
__device__ __nv_bfloat16 g_imh[(long)NIMG*BATCH*SEQ*KPATCH];
__device__ __nv_bfloat16 g_iml[(long)NIMG*BATCH*SEQ*KPATCH];
__device__ __nv_bfloat16 g_peh[(long)TOK*DIM];
__device__ __nv_bfloat16 g_pel[(long)TOK*DIM];
__device__ __nv_bfloat16 g_oh [(long)TOK*DIM];
__device__ __nv_bfloat16 g_ol [(long)TOK*DIM];
__device__ __nv_bfloat16 g_cwh[(long)NIMG*DIM*KPATCH];
__device__ __nv_bfloat16 g_cwl[(long)NIMG*DIM*KPATCH];
__device__ __nv_bfloat16 g_iwh[(long)NLAYER*3*DIM*DIM];
__device__ __nv_bfloat16 g_iwl[(long)NLAYER*3*DIM*DIM];
__device__ __nv_bfloat16 g_owh[(long)NLAYER*DIM*DIM];
__device__ __nv_bfloat16 g_owl[(long)NLAYER*DIM*DIM];
__device__ float g_qkv[(long)TOK*3*DIM];                 // 56.6 MB
__device__ float g_pe [(long)TOK*DIM];                   // 18.9 MB
__device__ float g_feat[BATCH*NIMG*DIM];

// ---------------- helpers ----------------
__device__ __forceinline__ unsigned f2tf(float f) {
    unsigned u; asm("cvt.rna.tf32.f32 %0, %1;" : "=r"(u) : "f"(f)); return u;
}
__device__ __forceinline__ void mma_tf32(float* d, const unsigned* a, unsigned b0, unsigned b1) {
    asm volatile(
        "mma.sync.aligned.m16n8k8.row.col.f32.tf32.tf32.f32 "
        "{%0,%1,%2,%3},{%4,%5,%6,%7},{%8,%9},{%0,%1,%2,%3};"
        : "+f"(d[0]), "+f"(d[1]), "+f"(d[2]), "+f"(d[3])
        : "r"(a[0]), "r"(a[1]), "r"(a[2]), "r"(a[3]), "r"(b0), "r"(b1));
}
__device__ __forceinline__ void mma_bf16(float* d, const unsigned* a, unsigned b0, unsigned b1) {
    asm volatile(
        "mma.sync.aligned.m16n8k16.row.col.f32.bf16.bf16.f32 "
        "{%0,%1,%2,%3},{%4,%5,%6,%7},{%8,%9},{%0,%1,%2,%3};"
        : "+f"(d[0]), "+f"(d[1]), "+f"(d[2]), "+f"(d[3])
        : "r"(a[0]), "r"(a[1]), "r"(a[2]), "r"(a[3]), "r"(b0), "r"(b1));
}
__device__ __forceinline__ void splitbf(float v, __nv_bfloat16& h, __nv_bfloat16& l) {
    h = __float2bfloat16(v);
    l = __float2bfloat16(v - __bfloat162float(h));
}
__device__ __forceinline__ void cp16(void* smem, const void* g) {
    unsigned s = (unsigned)__cvta_generic_to_shared(smem);
    asm volatile("cp.async.ca.shared.global [%0], [%1], 16;\n" :: "r"(s), "l"(g));
}

// ---------------- weight split kernel ----------------
__global__ void cvt_bf(const float* __restrict__ s,
                       __nv_bfloat16* __restrict__ h, __nv_bfloat16* __restrict__ l, int n) {
    int i = blockIdx.x*256 + threadIdx.x;
    if (i >= n) return;
    splitbf(s[i], h[i], l[i]);
}

// ---------------- im2col (split bf16 planes) ----------------
__global__ void im2col_k(const float* __restrict__ x) {
    long idx = (long)blockIdx.x*256 + threadIdx.x;
    const long total = (long)NIMG*BATCH*SEQ*KPATCH;
    if (idx >= total) return;
    int k   = (int)(idx % KPATCH);
    long r  = idx / KPATCH;
    int s   = (int)(r % SEQ);
    int b   = (int)((r / SEQ) % BATCH);
    int ni  = (int)(r / ((long)SEQ*BATCH));
    int c   = k >> 8;
    int py  = (k >> 4) & 15;
    int px  = k & 15;
    int gy  = s / GRID24, gx = s % GRID24;
    float v = x[(((long)b*12 + ni*3 + c)*384 + gy*16 + py)*384 + gx*16 + px];
    splitbf(v, g_imh[idx], g_iml[idx]);
}

// ---------------- bf16x3 tensor GEMM v2: 128x64 tile, cp.async double-buffer ----------------
// C[M,N] = A[M,K] @ Bw[N,K]^T. A/B as separate bf16 hi/lo planes.
// 256 threads, 8 warps each 32x32 output. M%128==0, N%64==0, K%32==0.
#define GSTR 40
#define GEMM_SMEM ((2*2*128*GSTR + 2*2*64*GSTR)*2)   // 61,440 B
__global__ __launch_bounds__(256, 2) void gemm_bf3(
    const __nv_bfloat16* __restrict__ Ah, const __nv_bfloat16* __restrict__ Al,
    const __nv_bfloat16* __restrict__ Bh, const __nv_bfloat16* __restrict__ Bl,
    float* __restrict__ Cf, __nv_bfloat16* __restrict__ Ch, __nv_bfloat16* __restrict__ Cl,
    int M, int N, int K,
    const float* __restrict__ bias, const float* __restrict__ pos,
    long strideA, long strideB, long strideC, int strideBias)
{
    Ah += (long)blockIdx.z * strideA;  Al += (long)blockIdx.z * strideA;
    Bh += (long)blockIdx.z * strideB;  Bl += (long)blockIdx.z * strideB;
    if (Cf) Cf += (long)blockIdx.z * strideC;
    if (Ch) { Ch += (long)blockIdx.z * strideC; Cl += (long)blockIdx.z * strideC; }
    if (bias) bias += (long)blockIdx.z * strideBias;

    extern __shared__ __nv_bfloat16 dyn[];
    __nv_bfloat16* sA = dyn;                       // [buf][plane][128][GSTR]
    __nv_bfloat16* sB = dyn + 2*2*128*GSTR;        // [buf][plane][64][GSTR]

    const int tid  = threadIdx.x;
    const int lane = tid & 31;
    const int w    = tid >> 5;
    const int r4   = lane >> 2;
    const int c4   = lane & 3;
    const int wm   = w & 3;        // 4 m-warps of 32 rows
    const int wn   = w >> 2;       // 2 n-warps of 32 cols
    const int m0   = blockIdx.y * 128, n0 = blockIdx.x * 64;

    const int KT = K >> 5;

    // issue one k-tile's loads into buffer `buf`
    auto issue_tile = [&](int kt, int buf) {
        int k0 = kt << 5;
        #pragma unroll
        for (int i = 0; i < 4; i++) {
            int idx = i*256 + tid;
            int c = idx & 3, r = (idx >> 2) & 127, p = idx >> 9;
            const __nv_bfloat16* src = (p ? Al : Ah) + (long)(m0 + r)*K + k0 + c*8;
            cp16(&sA[((buf*2 + p)*128 + r)*GSTR + c*8], src);
        }
        #pragma unroll
        for (int i = 0; i < 2; i++) {
            int idx = i*256 + tid;
            int c = idx & 3, r = (idx >> 2) & 63, p = idx >> 8;
            const __nv_bfloat16* src = (p ? Bl : Bh) + (long)(n0 + r)*K + k0 + c*8;
            cp16(&sB[((buf*2 + p)*64 + r)*GSTR + c*8], src);
        }
        asm volatile("cp.async.commit_group;\n");
    };

    float acc[2][4][4] = {};

    issue_tile(0, 0);
    for (int kt = 0; kt < KT; kt++) {
        if (kt + 1 < KT) {
            issue_tile(kt + 1, (kt + 1) & 1);
            asm volatile("cp.async.wait_group 1;\n");
        } else {
            asm volatile("cp.async.wait_group 0;\n");
        }
        __syncthreads();
        const int buf = kt & 1;
        const __nv_bfloat16* Abh = &sA[(buf*2 + 0)*128*GSTR];
        const __nv_bfloat16* Abl = &sA[(buf*2 + 1)*128*GSTR];
        const __nv_bfloat16* Bbh = &sB[(buf*2 + 0)*64*GSTR];
        const __nv_bfloat16* Bbl = &sB[(buf*2 + 1)*64*GSTR];
        #pragma unroll
        for (int kk = 0; kk < 2; kk++) {
            int kb = kk*16 + c4*2;
            unsigned ah[2][4], al[2][4];
            #pragma unroll
            for (int mt = 0; mt < 2; mt++) {
                int row = wm*32 + mt*16 + r4;
                ah[mt][0] = *(const unsigned*)&Abh[(row  )*GSTR + kb];
                ah[mt][1] = *(const unsigned*)&Abh[(row+8)*GSTR + kb];
                ah[mt][2] = *(const unsigned*)&Abh[(row  )*GSTR + kb + 8];
                ah[mt][3] = *(const unsigned*)&Abh[(row+8)*GSTR + kb + 8];
                al[mt][0] = *(const unsigned*)&Abl[(row  )*GSTR + kb];
                al[mt][1] = *(const unsigned*)&Abl[(row+8)*GSTR + kb];
                al[mt][2] = *(const unsigned*)&Abl[(row  )*GSTR + kb + 8];
                al[mt][3] = *(const unsigned*)&Abl[(row+8)*GSTR + kb + 8];
            }
            #pragma unroll
            for (int nt = 0; nt < 4; nt++) {
                int bc = wn*32 + nt*8 + r4;
                unsigned bh0 = *(const unsigned*)&Bbh[bc*GSTR + kb];
                unsigned bh1 = *(const unsigned*)&Bbh[bc*GSTR + kb + 8];
                unsigned bl0 = *(const unsigned*)&Bbl[bc*GSTR + kb];
                unsigned bl1 = *(const unsigned*)&Bbl[bc*GSTR + kb + 8];
                #pragma unroll
                for (int mt = 0; mt < 2; mt++) {
                    mma_bf16(acc[mt][nt], ah[mt], bh0, bh1);
                    mma_bf16(acc[mt][nt], al[mt], bh0, bh1);
                    mma_bf16(acc[mt][nt], ah[mt], bl0, bl1);
                }
            }
        }
        __syncthreads();
    }

    #pragma unroll
    for (int mt = 0; mt < 2; mt++) {
        #pragma unroll
        for (int nt = 0; nt < 4; nt++) {
            int n = n0 + wn*32 + nt*8 + c4*2;
            float bx = 0.f, by = 0.f;
            if (bias) { bx = bias[n]; by = bias[n+1]; }
            int row0 = m0 + wm*32 + mt*16 + r4, row1 = row0 + 8;
            float v00 = acc[mt][nt][0]+bx, v01 = acc[mt][nt][1]+by;
            float v10 = acc[mt][nt][2]+bx, v11 = acc[mt][nt][3]+by;
            if (pos) {
                const float* p0 = pos + (long)(row0 % SEQ)*DIM + n;
                const float* p1 = pos + (long)(row1 % SEQ)*DIM + n;
                v00 += p0[0]; v01 += p0[1]; v10 += p1[0]; v11 += p1[1];
            }
            if (Cf) {
                *(float2*)&Cf[(long)row0*N + n] = make_float2(v00, v01);
                *(float2*)&Cf[(long)row1*N + n] = make_float2(v10, v11);
            }
            if (Ch) {
                __nv_bfloat162 h0, l0, h1, l1;
                splitbf(v00, h0.x, l0.x); splitbf(v01, h0.y, l0.y);
                splitbf(v10, h1.x, l1.x); splitbf(v11, h1.y, l1.y);
                *(__nv_bfloat162*)&Ch[(long)row0*N + n] = h0;
                *(__nv_bfloat162*)&Cl[(long)row0*N + n] = l0;
                *(__nv_bfloat162*)&Ch[(long)row1*N + n] = h1;
                *(__nv_bfloat162*)&Cl[(long)row1*N + n] = l1;
            }
        }
    }
}

// ---------------- fused attention: unchanged from R8 (validated) ----------------
#define KSTRD 580
#define SSTRD 580
#define ATTN_FLOATS (3*32*580 + 256 + 256 + 96)
#define ATTN_SMEM (ATTN_FLOATS*4)   // 225,152 B

__global__ __launch_bounds__(512, 1) void attn_mma(
    const float* __restrict__ qkv, float* __restrict__ attn_out, int layer)
{
    extern __shared__ float sm[];
    unsigned* Kt   = (unsigned*)sm;
    unsigned* Vt   = (unsigned*)(sm + 32*KSTRD);
    float* Ss      = sm + 2*32*KSTRD;
    float* pbufA   = Ss + 32*SSTRD;
    float* pbufB   = pbufA + 256;
    float* rowmax  = pbufB + 256;
    float* rinv0   = rowmax + 32;
    float* rinv1   = rinv0 + 32;

    const int tid  = threadIdx.x;
    const int lane = tid & 31;
    const int w    = tid >> 5;
    const int r4   = lane >> 2;
    const int c4   = lane & 3;
    const int ws   = w >> 3;
    const int wk   = w & 7;
    const int qt   = blockIdx.x;
    const int nb   = blockIdx.y;
    const float* qbase = qkv + (long)nb*SEQ*768;
    const float SC = 0.17677669529663687f;

    float am[9][4];
    #pragma unroll
    for (int nt = 0; nt < 9; nt++)
        #pragma unroll
        for (int i = 0; i < 4; i++) am[nt][i] = 0.f;

    for (int h = 0; h < NHEAD; h++) {
        #pragma unroll 3
        for (int it = 0; it < 9; it++) {
            int key4 = (w + it*16)*4;
            const float* kp = qbase + (long)key4*768 + 256 + h*32 + lane;
            uint4 pk;
            pk.x = f2tf(kp[0]);
            pk.y = f2tf(kp[768]);
            pk.z = f2tf(kp[2*768]);
            pk.w = f2tf(kp[3*768]);
            *(uint4*)&Kt[lane*KSTRD + key4] = pk;
            const float* vp = kp + 256;
            uint4 pv;
            pv.x = f2tf(vp[0]);
            pv.y = f2tf(vp[768]);
            pv.z = f2tf(vp[2*768]);
            pv.w = f2tf(vp[3*768]);
            *(uint4*)&Vt[lane*KSTRD + key4] = pv;
        }
        __syncthreads();                        // S1

        float acc[9][4];
        #pragma unroll
        for (int nt = 0; nt < 9; nt++)
            #pragma unroll
            for (int i = 0; i < 4; i++) acc[nt][i] = 0.f;

        #pragma unroll
        for (int kc = 0; kc < 4; kc++) {
            unsigned ah[4], al[4];
            {
                const float* qp = qbase + (long)(qt*32 + ws*16 + r4)*768 + h*32 + kc*8 + c4;
                float q0 = qp[0]*SC, q1 = qp[8*768]*SC, q2 = qp[4]*SC, q3 = qp[8*768+4]*SC;
                ah[0]=f2tf(q0); al[0]=f2tf(q0-__uint_as_float(ah[0]));
                ah[1]=f2tf(q1); al[1]=f2tf(q1-__uint_as_float(ah[1]));
                ah[2]=f2tf(q2); al[2]=f2tf(q2-__uint_as_float(ah[2]));
                ah[3]=f2tf(q3); al[3]=f2tf(q3-__uint_as_float(ah[3]));
            }
            const unsigned* kb  = &Kt[(kc*8 + c4)*KSTRD + wk*72 + r4];
            const unsigned* kb4 = kb + 4*KSTRD;
            #pragma unroll
            for (int nt = 0; nt < 9; nt++) {
                unsigned b0 = kb[nt*8], b1 = kb4[nt*8];
                mma_tf32(acc[nt], ah, b0, b1);
                mma_tf32(acc[nt], al, b0, b1);
            }
        }
        {
            float pm[2] = {-1e30f, -1e30f};
            #pragma unroll
            for (int nt = 0; nt < 9; nt++) {
                pm[0] = fmaxf(pm[0], fmaxf(acc[nt][0], acc[nt][1]));
                pm[1] = fmaxf(pm[1], fmaxf(acc[nt][2], acc[nt][3]));
            }
            #pragma unroll
            for (int s = 0; s < 2; s++) {
                pm[s] = fmaxf(pm[s], __shfl_xor_sync(0xffffffffu, pm[s], 1));
                pm[s] = fmaxf(pm[s], __shfl_xor_sync(0xffffffffu, pm[s], 2));
            }
            if (c4 == 0) {
                pbufA[(ws*16 + r4)*8 + wk]     = pm[0];
                pbufA[(ws*16 + 8 + r4)*8 + wk] = pm[1];
            }
        }
        __syncthreads();                        // S2
        if (tid < 32) {
            float m = pbufA[tid*8];
            #pragma unroll
            for (int i = 1; i < 8; i++) m = fmaxf(m, pbufA[tid*8 + i]);
            rowmax[tid] = m;
        }
        __syncthreads();                        // S3
        {
            float rm0 = rowmax[ws*16 + r4], rm1 = rowmax[ws*16 + 8 + r4];
            float psA[2] = {0.f,0.f};
            float psB[2] = {0.f,0.f};
            float* row0 = &Ss[(ws*16 + r4)*SSTRD + wk*72 + c4*2];
            float* row1 = row0 + 8*SSTRD;
            #pragma unroll
            for (int nt = 0; nt < 9; nt++) {
                float e0 = __expf(acc[nt][0] - rm0);
                float e1 = __expf(acc[nt][1] - rm0);
                float e2 = __expf(acc[nt][2] - rm1);
                float e3 = __expf(acc[nt][3] - rm1);
                acc[nt][0] = e0; acc[nt][1] = e1;
                acc[nt][2] = e2; acc[nt][3] = e3;
                psA[0] += e0 + e1;
                psA[1] += e2 + e3;
                float f0  = __uint_as_float(f2tf(e0));
                float f1  = __uint_as_float(f2tf(e1));
                float f2v = __uint_as_float(f2tf(e2));
                float f3  = __uint_as_float(f2tf(e3));
                psB[0] += f0 + f1;
                psB[1] += f2v + f3;
                *(float2*)&row0[nt*8] = make_float2(f0, f1);
                *(float2*)&row1[nt*8] = make_float2(f2v, f3);
            }
            #pragma unroll
            for (int s = 0; s < 2; s++) {
                psA[s] += __shfl_xor_sync(0xffffffffu, psA[s], 1);
                psA[s] += __shfl_xor_sync(0xffffffffu, psA[s], 2);
                psB[s] += __shfl_xor_sync(0xffffffffu, psB[s], 1);
                psB[s] += __shfl_xor_sync(0xffffffffu, psB[s], 2);
            }
            if (c4 == 0) {
                pbufA[(ws*16 + r4)*8 + wk]     = psA[0];
                pbufA[(ws*16 + 8 + r4)*8 + wk] = psA[1];
                pbufB[(ws*16 + r4)*8 + wk]     = psB[0];
                pbufB[(ws*16 + 8 + r4)*8 + wk] = psB[1];
            }
        }
        __syncthreads();                        // S4
        if (tid < 32) {
            float sa = 0.f, sb = 0.f;
            #pragma unroll
            for (int i = 0; i < 8; i++) { sa += pbufA[tid*8 + i]; sb += pbufB[tid*8 + i]; }
            rinv0[tid] = __frcp_rn(sa);
            rinv1[tid] = __frcp_rn(sb);
        }
        __syncthreads();                        // S5
        {
            float ra0 = rinv0[ws*16 + r4]*0.125f, ra1 = rinv0[ws*16 + 8 + r4]*0.125f;
            #pragma unroll
            for (int nt = 0; nt < 9; nt++) {
                am[nt][0] += acc[nt][0] * ra0;
                am[nt][1] += acc[nt][1] * ra0;
                am[nt][2] += acc[nt][2] * ra1;
                am[nt][3] += acc[nt][3] * ra1;
            }
        }
        {
            const int nt6 = w & 3, half = (w >> 2) & 1, mt = w >> 3;
            float dv[4] = {0.f, 0.f, 0.f, 0.f};
            const unsigned* Es  = (const unsigned*)Ss;
            const unsigned* e0b = &Es[(mt*16 + r4)*SSTRD + half*288 + c4];
            const unsigned* e1b = e0b + 8*SSTRD;
            const unsigned* vb  = &Vt[(nt6*8 + r4)*KSTRD + half*288 + c4];
            #pragma unroll 6
            for (int kc = 0; kc < 36; kc++) {
                unsigned a[4];
                a[0] = e0b[kc*8]; a[1] = e1b[kc*8];
                a[2] = e0b[kc*8 + 4]; a[3] = e1b[kc*8 + 4];
                mma_tf32(dv, a, vb[kc*8], vb[kc*8 + 4]);
            }
            __syncthreads();                    // S6a
            if (half == 1)
                *(float4*)&Ss[((mt*4 + nt6)*32 + lane)*4] = make_float4(dv[0], dv[1], dv[2], dv[3]);
            __syncthreads();                    // S6b
            if (half == 0) {
                float4 p = *(float4*)&Ss[((mt*4 + nt6)*32 + lane)*4];
                dv[0] += p.x; dv[1] += p.y; dv[2] += p.z; dv[3] += p.w;
                float ri0 = rinv1[mt*16 + r4], ri1 = rinv1[mt*16 + 8 + r4];
                float x0 = dv[0]*ri0, x1 = dv[1]*ri0;
                float x2 = dv[2]*ri1, x3 = dv[3]*ri1;
                long orow = (long)(nb*SEQ + qt*32 + mt*16 + r4)*DIM + h*32 + nt6*8 + c4*2;
                __nv_bfloat162 h0, l0, h1, l1;
                splitbf(x0, h0.x, l0.x); splitbf(x1, h0.y, l0.y);
                splitbf(x2, h1.x, l1.x); splitbf(x3, h1.y, l1.y);
                *(__nv_bfloat162*)&g_oh[orow]         = h0;
                *(__nv_bfloat162*)&g_ol[orow]         = l0;
                *(__nv_bfloat162*)&g_oh[orow + 8*DIM] = h1;
                *(__nv_bfloat162*)&g_ol[orow + 8*DIM] = l1;
            }
        }
    }
    float* aout = attn_out + (long)(layer*NB + nb)*SEQ*SEQ + (long)qt*32*SEQ;
    #pragma unroll
    for (int nt = 0; nt < 9; nt++) {
        int col = wk*72 + nt*8 + c4*2;
        *(float2*)&aout[(long)(ws*16 + r4)*SEQ + col]     = make_float2(am[nt][0], am[nt][1]);
        *(float2*)&aout[(long)(ws*16 + 8 + r4)*SEQ + col] = make_float2(am[nt][2], am[nt][3]);
    }
}

// ---------------- feature mean over sequence ----------------
__global__ void feat_k(void) {
    int ni = blockIdx.x, b = blockIdx.y, d = threadIdx.x;
    const float* p = g_pe + ((long)(ni*BATCH + b)*SEQ)*DIM + d;
    float s = 0.f;
    for (int t = 0; t < SEQ; t++) s += p[(long)t*DIM];
    g_feat[b*(NIMG*DIM) + ni*DIM + d] = s * (1.0f/576.0f);
}

// ---------------- MLP head ----------------
__global__ void head_k(const float* __restrict__ w1, const float* __restrict__ b1,
                       const float* __restrict__ w2, const float* __restrict__ b2,
                       float* __restrict__ out) {
    __shared__ float fs[NIMG*DIM];
    __shared__ float hs[MLPDIM];
    int b = blockIdx.x, tid = threadIdx.x;
    for (int t = tid; t < NIMG*DIM; t += MLPDIM) fs[t] = g_feat[b*NIMG*DIM + t];
    __syncthreads();
    float a = b1[tid];
    const float* wr = w1 + (long)tid*(NIMG*DIM);
    for (int d2 = 0; d2 < NIMG*DIM; d2++) a += fs[d2]*wr[d2];
    hs[tid] = fmaxf(a, 0.f) * w2[tid];
    __syncthreads();
    for (int st = 256; st > 0; st >>= 1) {
        if (tid < st) hs[tid] += hs[tid + st];
        __syncthreads();
    }
    if (tid == 0) out[b] = hs[0] + b2[0];
}

// ---------------- launch ----------------
extern "C" void kernel_launch(void* const* d_in, const int* in_sizes, int n_in,
                              void* d_out, int out_size) {
    const float* x      = (const float*)d_in[0];
    const float* conv_w = (const float*)d_in[1];
    const float* conv_b = (const float*)d_in[2];
    const float* pos_e  = (const float*)d_in[3];
    const float* in_w   = (const float*)d_in[4];
    const float* in_b   = (const float*)d_in[5];
    const float* out_w  = (const float*)d_in[6];
    const float* out_b  = (const float*)d_in[7];
    const float* hw1    = (const float*)d_in[8];
    const float* hb1    = (const float*)d_in[9];
    const float* hw2    = (const float*)d_in[10];
    const float* hb2    = (const float*)d_in[11];

    float* out  = (float*)d_out;            // [8]
    float* attn = out + BATCH;              // [6,4,8,576,576]

    cudaFuncSetAttribute(attn_mma, cudaFuncAttributeMaxDynamicSharedMemorySize, ATTN_SMEM);
    cudaFuncSetAttribute(gemm_bf3, cudaFuncAttributeMaxDynamicSharedMemorySize, GEMM_SMEM);

    __nv_bfloat16 *imh_p, *iml_p, *peh_p, *pel_p, *oh_p, *ol_p;
    __nv_bfloat16 *cwh_p, *cwl_p, *iwh_p, *iwl_p, *owh_p, *owl_p;
    float *qkv_p, *pe_p;
    cudaGetSymbolAddress((void**)&imh_p, g_imh);
    cudaGetSymbolAddress((void**)&iml_p, g_iml);
    cudaGetSymbolAddress((void**)&peh_p, g_peh);
    cudaGetSymbolAddress((void**)&pel_p, g_pel);
    cudaGetSymbolAddress((void**)&oh_p,  g_oh);
    cudaGetSymbolAddress((void**)&ol_p,  g_ol);
    cudaGetSymbolAddress((void**)&cwh_p, g_cwh);
    cudaGetSymbolAddress((void**)&cwl_p, g_cwl);
    cudaGetSymbolAddress((void**)&iwh_p, g_iwh);
    cudaGetSymbolAddress((void**)&iwl_p, g_iwl);
    cudaGetSymbolAddress((void**)&owh_p, g_owh);
    cudaGetSymbolAddress((void**)&owl_p, g_owl);
    cudaGetSymbolAddress((void**)&qkv_p, g_qkv);
    cudaGetSymbolAddress((void**)&pe_p,  g_pe);

    // 0) weight splits
    cvt_bf<<<(NIMG*DIM*KPATCH + 255)/256, 256>>>(conv_w, cwh_p, cwl_p, NIMG*DIM*KPATCH);
    cvt_bf<<<(NLAYER*3*DIM*DIM + 255)/256, 256>>>(in_w, iwh_p, iwl_p, NLAYER*3*DIM*DIM);
    cvt_bf<<<(NLAYER*DIM*DIM + 255)/256, 256>>>(out_w, owh_p, owl_p, NLAYER*DIM*DIM);

    // 1) im2col (split)
    {
        long total = (long)NIMG*BATCH*SEQ*KPATCH;
        im2col_k<<<(int)((total + 255)/256), 256>>>(x);
    }
    // 2) patch-embed GEMM per image (+conv_b +pos) -> peh/pel
    {
        dim3 g(DIM/64, (BATCH*SEQ)/128, NIMG);
        gemm_bf3<<<g, 256, GEMM_SMEM>>>(imh_p, iml_p, cwh_p, cwl_p,
                             nullptr, peh_p, pel_p,
                             BATCH*SEQ, DIM, KPATCH,
                             conv_b, pos_e,
                             (long)BATCH*SEQ*KPATCH, (long)DIM*KPATCH,
                             (long)BATCH*SEQ*DIM, DIM);
    }
    // 3) transformer layers
    for (int l = 0; l < NLAYER; l++) {
        {   // qkv: (peh,pel) x in_w -> f32 qkv
            dim3 g((3*DIM)/64, TOK/128, 1);
            gemm_bf3<<<g, 256, GEMM_SMEM>>>(peh_p, pel_p,
                                 iwh_p + (long)l*3*DIM*DIM, iwl_p + (long)l*3*DIM*DIM,
                                 qkv_p, nullptr, nullptr,
                                 TOK, 3*DIM, DIM,
                                 in_b + (long)l*3*DIM, nullptr, 0, 0, 0, 0);
        }
        {
            dim3 g(SEQ/32, NB, 1);
            attn_mma<<<g, 512, ATTN_SMEM>>>(qkv_p, attn, l);
        }
        {   // out-proj: (oh,ol) x out_w -> pe f32 + peh/pel
            dim3 g(DIM/64, TOK/128, 1);
            gemm_bf3<<<g, 256, GEMM_SMEM>>>(oh_p, ol_p,
                                 owh_p + (long)l*DIM*DIM, owl_p + (long)l*DIM*DIM,
                                 pe_p, peh_p, pel_p,
                                 TOK, DIM, DIM,
                                 out_b + (long)l*DIM, nullptr, 0, 0, 0, 0);
        }
    }
    // 4) sequence-mean features + MLP head
    {
        dim3 g(NIMG, BATCH);
        feat_k<<<g, DIM>>>();
    }
    head_k<<<BATCH, MLPDIM>>>(hw1, hb1, hw2, hb2, out);
}

// round 10
// speedup vs baseline: 1.6910x; 1.6910x over previous
#include <cuda_runtime.h>
#include <cuda_bf16.h>
#include <math.h>

// ---------------- problem constants ----------------
#define NIMG 4
#define BATCH 8
#define SEQ 576
#define DIM 256
#define NHEAD 8
#define DHEAD 32
#define NLAYER 6
#define MLPDIM 512
#define NB (NIMG*BATCH)      // 32
#define TOK (NB*SEQ)         // 18432
#define KPATCH 768           // 3*16*16
#define GRID24 24

// ---------------- scratch (device globals; no allocation allowed) ----------------
__device__ __nv_bfloat16 g_imh[(long)NIMG*BATCH*SEQ*KPATCH];
__device__ __nv_bfloat16 g_iml[(long)NIMG*BATCH*SEQ*KPATCH];
__device__ __nv_bfloat16 g_peh[(long)TOK*DIM];
__device__ __nv_bfloat16 g_pel[(long)TOK*DIM];
__device__ __nv_bfloat16 g_oh [(long)TOK*DIM];
__device__ __nv_bfloat16 g_ol [(long)TOK*DIM];
__device__ __nv_bfloat16 g_cwh[(long)NIMG*DIM*KPATCH];
__device__ __nv_bfloat16 g_cwl[(long)NIMG*DIM*KPATCH];
__device__ __nv_bfloat16 g_iwh[(long)NLAYER*3*DIM*DIM];
__device__ __nv_bfloat16 g_iwl[(long)NLAYER*3*DIM*DIM];
__device__ __nv_bfloat16 g_owh[(long)NLAYER*DIM*DIM];
__device__ __nv_bfloat16 g_owl[(long)NLAYER*DIM*DIM];
__device__ float g_qkv[(long)TOK*3*DIM];                 // 56.6 MB
__device__ float g_pe [(long)TOK*DIM];                   // 18.9 MB
__device__ float g_feat[BATCH*NIMG*DIM];

// ---------------- helpers ----------------
__device__ __forceinline__ unsigned f2tf(float f) {
    unsigned u; asm("cvt.rna.tf32.f32 %0, %1;" : "=r"(u) : "f"(f)); return u;
}
__device__ __forceinline__ void mma_tf32(float* d, const unsigned* a, unsigned b0, unsigned b1) {
    asm volatile(
        "mma.sync.aligned.m16n8k8.row.col.f32.tf32.tf32.f32 "
        "{%0,%1,%2,%3},{%4,%5,%6,%7},{%8,%9},{%0,%1,%2,%3};"
        : "+f"(d[0]), "+f"(d[1]), "+f"(d[2]), "+f"(d[3])
        : "r"(a[0]), "r"(a[1]), "r"(a[2]), "r"(a[3]), "r"(b0), "r"(b1));
}
__device__ __forceinline__ void mma_bf16(float* d, const unsigned* a, unsigned b0, unsigned b1) {
    asm volatile(
        "mma.sync.aligned.m16n8k16.row.col.f32.bf16.bf16.f32 "
        "{%0,%1,%2,%3},{%4,%5,%6,%7},{%8,%9},{%0,%1,%2,%3};"
        : "+f"(d[0]), "+f"(d[1]), "+f"(d[2]), "+f"(d[3])
        : "r"(a[0]), "r"(a[1]), "r"(a[2]), "r"(a[3]), "r"(b0), "r"(b1));
}
__device__ __forceinline__ void mma_bf16_k8(float* d, const unsigned* a, unsigned b0) {
    asm volatile(
        "mma.sync.aligned.m16n8k8.row.col.f32.bf16.bf16.f32 "
        "{%0,%1,%2,%3},{%4,%5},{%6},{%0,%1,%2,%3};"
        : "+f"(d[0]), "+f"(d[1]), "+f"(d[2]), "+f"(d[3])
        : "r"(a[0]), "r"(a[1]), "r"(b0));
}
__device__ __forceinline__ void splitbf(float v, __nv_bfloat16& h, __nv_bfloat16& l) {
    h = __float2bfloat16(v);
    l = __float2bfloat16(v - __bfloat162float(h));
}

// ---------------- weight split kernel ----------------
__global__ void cvt_bf(const float* __restrict__ s,
                       __nv_bfloat16* __restrict__ h, __nv_bfloat16* __restrict__ l, int n) {
    int i = blockIdx.x*256 + threadIdx.x;
    if (i >= n) return;
    splitbf(s[i], h[i], l[i]);
}

// ---------------- im2col (split bf16 planes) ----------------
__global__ void im2col_k(const float* __restrict__ x) {
    long idx = (long)blockIdx.x*256 + threadIdx.x;
    const long total = (long)NIMG*BATCH*SEQ*KPATCH;
    if (idx >= total) return;
    int k   = (int)(idx % KPATCH);
    long r  = idx / KPATCH;
    int s   = (int)(r % SEQ);
    int b   = (int)((r / SEQ) % BATCH);
    int ni  = (int)(r / ((long)SEQ*BATCH));
    int c   = k >> 8;
    int py  = (k >> 4) & 15;
    int px  = k & 15;
    int gy  = s / GRID24, gx = s % GRID24;
    float v = x[(((long)b*12 + ni*3 + c)*384 + gy*16 + py)*384 + gx*16 + px];
    splitbf(v, g_imh[idx], g_iml[idx]);
}

// ---------------- bf16x3 tensor GEMM (R8-validated): 64x64 tile ----------------
#define BSTR 40
__global__ __launch_bounds__(256) void gemm_bf3(
    const __nv_bfloat16* __restrict__ Ah, const __nv_bfloat16* __restrict__ Al,
    const __nv_bfloat16* __restrict__ Bh, const __nv_bfloat16* __restrict__ Bl,
    float* __restrict__ Cf, __nv_bfloat16* __restrict__ Ch, __nv_bfloat16* __restrict__ Cl,
    int M, int N, int K,
    const float* __restrict__ bias, const float* __restrict__ pos,
    long strideA, long strideB, long strideC, int strideBias)
{
    Ah += (long)blockIdx.z * strideA;  Al += (long)blockIdx.z * strideA;
    Bh += (long)blockIdx.z * strideB;  Bl += (long)blockIdx.z * strideB;
    if (Cf) Cf += (long)blockIdx.z * strideC;
    if (Ch) { Ch += (long)blockIdx.z * strideC; Cl += (long)blockIdx.z * strideC; }
    if (bias) bias += (long)blockIdx.z * strideBias;

    __shared__ __nv_bfloat16 sAh[64][BSTR], sAl[64][BSTR];
    __shared__ __nv_bfloat16 sBh[64][BSTR], sBl[64][BSTR];

    const int tid  = threadIdx.x;
    const int lane = tid & 31;
    const int w    = tid >> 5;
    const int r4   = lane >> 2;
    const int c4   = lane & 3;
    const int wm   = w & 3, wn = w >> 2;
    const int m0   = blockIdx.y * 64, n0 = blockIdx.x * 64;
    const int lrow = tid >> 2;
    const int lk8  = (tid & 3) * 8;

    float acc[4][4] = {};

    for (int k0 = 0; k0 < K; k0 += 32) {
        long ga = (long)(m0 + lrow)*K + k0 + lk8;
        long gb = (long)(n0 + lrow)*K + k0 + lk8;
        *(uint4*)&sAh[lrow][lk8] = *(const uint4*)&Ah[ga];
        *(uint4*)&sAl[lrow][lk8] = *(const uint4*)&Al[ga];
        *(uint4*)&sBh[lrow][lk8] = *(const uint4*)&Bh[gb];
        *(uint4*)&sBl[lrow][lk8] = *(const uint4*)&Bl[gb];
        __syncthreads();
        #pragma unroll
        for (int kk = 0; kk < 2; kk++) {
            int kb = kk*16 + c4*2;
            int ar0 = wm*16 + r4, ar1 = ar0 + 8;
            unsigned ah[4], al[4];
            ah[0] = *(const unsigned*)&sAh[ar0][kb];
            ah[1] = *(const unsigned*)&sAh[ar1][kb];
            ah[2] = *(const unsigned*)&sAh[ar0][kb+8];
            ah[3] = *(const unsigned*)&sAh[ar1][kb+8];
            al[0] = *(const unsigned*)&sAl[ar0][kb];
            al[1] = *(const unsigned*)&sAl[ar1][kb];
            al[2] = *(const unsigned*)&sAl[ar0][kb+8];
            al[3] = *(const unsigned*)&sAl[ar1][kb+8];
            #pragma unroll
            for (int nt = 0; nt < 4; nt++) {
                int bc = wn*32 + nt*8 + r4;
                unsigned bh0 = *(const unsigned*)&sBh[bc][kb];
                unsigned bh1 = *(const unsigned*)&sBh[bc][kb+8];
                unsigned bl0 = *(const unsigned*)&sBl[bc][kb];
                unsigned bl1 = *(const unsigned*)&sBl[bc][kb+8];
                mma_bf16(acc[nt], ah, bh0, bh1);
                mma_bf16(acc[nt], al, bh0, bh1);
                mma_bf16(acc[nt], ah, bl0, bl1);
            }
        }
        __syncthreads();
    }

    #pragma unroll
    for (int nt = 0; nt < 4; nt++) {
        int n = n0 + wn*32 + nt*8 + c4*2;
        float bx = 0.f, by = 0.f;
        if (bias) { bx = bias[n]; by = bias[n+1]; }
        int row0 = m0 + wm*16 + r4, row1 = row0 + 8;
        float v00 = acc[nt][0]+bx, v01 = acc[nt][1]+by;
        float v10 = acc[nt][2]+bx, v11 = acc[nt][3]+by;
        if (pos) {
            const float* p0 = pos + (long)(row0 % SEQ)*DIM + n;
            const float* p1 = pos + (long)(row1 % SEQ)*DIM + n;
            v00 += p0[0]; v01 += p0[1]; v10 += p1[0]; v11 += p1[1];
        }
        if (Cf) {
            *(float2*)&Cf[(long)row0*N + n] = make_float2(v00, v01);
            *(float2*)&Cf[(long)row1*N + n] = make_float2(v10, v11);
        }
        if (Ch) {
            __nv_bfloat162 h0, l0, h1, l1;
            splitbf(v00, h0.x, l0.x); splitbf(v01, h0.y, l0.y);
            splitbf(v10, h1.x, l1.x); splitbf(v11, h1.y, l1.y);
            *(__nv_bfloat162*)&Ch[(long)row0*N + n] = h0;
            *(__nv_bfloat162*)&Cl[(long)row0*N + n] = l0;
            *(__nv_bfloat162*)&Ch[(long)row1*N + n] = h1;
            *(__nv_bfloat162*)&Cl[(long)row1*N + n] = l1;
        }
    }
}

// ---------------- fused attention: register-resident E (FA2-style PV) ----------------
#define KSTRD 580
#define VSTR  292
// floats: Kt 18560 + Vh 9344 + Vl 9344 + pbufA 256 + rowmax 32 + rinv 32
#define ATTN_FLOATS (32*KSTRD + 2*32*VSTR + 256 + 32 + 32)
#define ATTN_SMEM (ATTN_FLOATS*4)   // 150,272 B

__global__ __launch_bounds__(512, 1) void attn_mma(
    const float* __restrict__ qkv, float* __restrict__ attn_out, int layer)
{
    extern __shared__ float sm[];
    unsigned* Kt   = (unsigned*)sm;                  // [32 dh][580] tf32 K^T; buf overlay
    unsigned* Vh   = Kt + 32*KSTRD;                  // [32 dh][292] bf16-pair V^T hi
    unsigned* Vl   = Vh + 32*VSTR;                   // [32 dh][292] bf16-pair V^T lo
    float* pbufA   = sm + 32*KSTRD + 2*32*VSTR;      // [32][8]
    float* rowmax  = pbufA + 256;                    // [32]
    float* rinv    = rowmax + 32;                    // [32]
    float* buf     = (float*)Kt;                     // PV partial-O scratch (32 KB)

    const int tid  = threadIdx.x;
    const int lane = tid & 31;
    const int w    = tid >> 5;                  // 0..15
    const int r4   = lane >> 2;
    const int c4   = lane & 3;
    const int ws   = w >> 3;                    // q-subtile (16 q)
    const int wk   = w & 7;                     // key-slice (72 keys)
    const int qt   = blockIdx.x;                // 0..17
    const int nb   = blockIdx.y;                // 0..31
    const float* qbase = qkv + (long)nb*SEQ*768;
    const float SC = 0.17677669529663687f;      // 1/sqrt(32)

    float am[9][4];
    #pragma unroll
    for (int nt = 0; nt < 9; nt++)
        #pragma unroll
        for (int i = 0; i < 4; i++) am[nt][i] = 0.f;

    for (int h = 0; h < NHEAD; h++) {
        // ---- P1: K^T as tf32; V^T as packed bf16 hi/lo pairs ----
        #pragma unroll 3
        for (int it = 0; it < 9; it++) {
            int key4 = (w + it*16)*4;
            const float* kp = qbase + (long)key4*768 + 256 + h*32 + lane;
            uint4 pk;
            pk.x = f2tf(kp[0]);
            pk.y = f2tf(kp[768]);
            pk.z = f2tf(kp[2*768]);
            pk.w = f2tf(kp[3*768]);
            *(uint4*)&Kt[lane*KSTRD + key4] = pk;
            const float* vp = kp + 256;
            float v0 = vp[0], v1 = vp[768], v2 = vp[2*768], v3 = vp[3*768];
            __nv_bfloat162 h01 = __floats2bfloat162_rn(v0, v1);
            __nv_bfloat162 h23 = __floats2bfloat162_rn(v2, v3);
            __nv_bfloat162 l01 = __floats2bfloat162_rn(v0 - __bfloat162float(h01.x),
                                                       v1 - __bfloat162float(h01.y));
            __nv_bfloat162 l23 = __floats2bfloat162_rn(v2 - __bfloat162float(h23.x),
                                                       v3 - __bfloat162float(h23.y));
            uint2 ph; ph.x = *(unsigned*)&h01; ph.y = *(unsigned*)&h23;
            uint2 pl; pl.x = *(unsigned*)&l01; pl.y = *(unsigned*)&l23;
            *(uint2*)&Vh[lane*VSTR + key4/2] = ph;
            *(uint2*)&Vl[lane*VSTR + key4/2] = pl;
        }
        __syncthreads();                        // S1

        // ---- P2: S = Q K^T (Q hi/lo tf32 split); warp (ws,wk) -> 16q x 72k ----
        float acc[9][4];
        #pragma unroll
        for (int nt = 0; nt < 9; nt++)
            #pragma unroll
            for (int i = 0; i < 4; i++) acc[nt][i] = 0.f;

        #pragma unroll
        for (int kc = 0; kc < 4; kc++) {
            unsigned ah[4], al[4];
            {
                const float* qp = qbase + (long)(qt*32 + ws*16 + r4)*768 + h*32 + kc*8 + c4;
                float q0 = qp[0]*SC, q1 = qp[8*768]*SC, q2 = qp[4]*SC, q3 = qp[8*768+4]*SC;
                ah[0]=f2tf(q0); al[0]=f2tf(q0-__uint_as_float(ah[0]));
                ah[1]=f2tf(q1); al[1]=f2tf(q1-__uint_as_float(ah[1]));
                ah[2]=f2tf(q2); al[2]=f2tf(q2-__uint_as_float(ah[2]));
                ah[3]=f2tf(q3); al[3]=f2tf(q3-__uint_as_float(ah[3]));
            }
            const unsigned* kb  = &Kt[(kc*8 + c4)*KSTRD + wk*72 + r4];
            const unsigned* kb4 = kb + 4*KSTRD;
            #pragma unroll
            for (int nt = 0; nt < 9; nt++) {
                unsigned b0 = kb[nt*8], b1 = kb4[nt*8];
                mma_tf32(acc[nt], ah, b0, b1);
                mma_tf32(acc[nt], al, b0, b1);
            }
        }
        // partial row max
        {
            float pm[2] = {-1e30f, -1e30f};
            #pragma unroll
            for (int nt = 0; nt < 9; nt++) {
                pm[0] = fmaxf(pm[0], fmaxf(acc[nt][0], acc[nt][1]));
                pm[1] = fmaxf(pm[1], fmaxf(acc[nt][2], acc[nt][3]));
            }
            #pragma unroll
            for (int s = 0; s < 2; s++) {
                pm[s] = fmaxf(pm[s], __shfl_xor_sync(0xffffffffu, pm[s], 1));
                pm[s] = fmaxf(pm[s], __shfl_xor_sync(0xffffffffu, pm[s], 2));
            }
            if (c4 == 0) {
                pbufA[(ws*16 + r4)*8 + wk]     = pm[0];
                pbufA[(ws*16 + 8 + r4)*8 + wk] = pm[1];
            }
        }
        __syncthreads();                        // S2
        if (tid < 32) {
            float m = pbufA[tid*8];
            #pragma unroll
            for (int i = 1; i < 8; i++) m = fmaxf(m, pbufA[tid*8 + i]);
            rowmax[tid] = m;
        }
        __syncthreads();                        // S3
        // ---- P4: e = exp(s - rowmax) in registers; row sums ----
        {
            float rm0 = rowmax[ws*16 + r4], rm1 = rowmax[ws*16 + 8 + r4];
            float ps[2] = {0.f, 0.f};
            #pragma unroll
            for (int nt = 0; nt < 9; nt++) {
                float e0 = __expf(acc[nt][0] - rm0);
                float e1 = __expf(acc[nt][1] - rm0);
                float e2 = __expf(acc[nt][2] - rm1);
                float e3 = __expf(acc[nt][3] - rm1);
                acc[nt][0] = e0; acc[nt][1] = e1;
                acc[nt][2] = e2; acc[nt][3] = e3;
                ps[0] += e0 + e1;
                ps[1] += e2 + e3;
            }
            #pragma unroll
            for (int s = 0; s < 2; s++) {
                ps[s] += __shfl_xor_sync(0xffffffffu, ps[s], 1);
                ps[s] += __shfl_xor_sync(0xffffffffu, ps[s], 2);
            }
            if (c4 == 0) {
                pbufA[(ws*16 + r4)*8 + wk]     = ps[0];
                pbufA[(ws*16 + 8 + r4)*8 + wk] = ps[1];
            }
        }
        __syncthreads();                        // S4
        if (tid < 32) {
            float sa = 0.f;
            #pragma unroll
            for (int i = 0; i < 8; i++) sa += pbufA[tid*8 + i];
            rinv[tid] = __frcp_rn(sa);
        }
        __syncthreads();                        // S5
        // ---- P5: Am += e * rinv / 8 (registers) ----
        {
            float ra0 = rinv[ws*16 + r4]*0.125f, ra1 = rinv[ws*16 + 8 + r4]*0.125f;
            #pragma unroll
            for (int nt = 0; nt < 9; nt++) {
                am[nt][0] += acc[nt][0] * ra0;
                am[nt][1] += acc[nt][1] * ra0;
                am[nt][2] += acc[nt][2] * ra1;
                am[nt][3] += acc[nt][3] * ra1;
            }
        }
        // ---- pack E into bf16 hi/lo fragments (registers; acc dies here) ----
        unsigned eh[9][2], el[9][2];
        #pragma unroll
        for (int nt = 0; nt < 9; nt++) {
            __nv_bfloat162 h01 = __floats2bfloat162_rn(acc[nt][0], acc[nt][1]);
            __nv_bfloat162 h23 = __floats2bfloat162_rn(acc[nt][2], acc[nt][3]);
            __nv_bfloat162 l01 = __floats2bfloat162_rn(acc[nt][0] - __bfloat162float(h01.x),
                                                       acc[nt][1] - __bfloat162float(h01.y));
            __nv_bfloat162 l23 = __floats2bfloat162_rn(acc[nt][2] - __bfloat162float(h23.x),
                                                       acc[nt][3] - __bfloat162float(h23.y));
            eh[nt][0] = *(unsigned*)&h01; eh[nt][1] = *(unsigned*)&h23;
            el[nt][0] = *(unsigned*)&l01; el[nt][1] = *(unsigned*)&l23;
        }
        // ---- PV: partial O[16q x 32dh] over this warp's 72 keys ----
        float po[4][4] = {};
        #pragma unroll
        for (int nt6 = 0; nt6 < 4; nt6++) {
            const unsigned* vbh = &Vh[(nt6*8 + r4)*VSTR + wk*36 + c4];
            const unsigned* vbl = &Vl[(nt6*8 + r4)*VSTR + wk*36 + c4];
            #pragma unroll
            for (int s = 0; s < 4; s++) {
                unsigned a_h[4] = {eh[2*s][0], eh[2*s][1], eh[2*s+1][0], eh[2*s+1][1]};
                unsigned a_l[4] = {el[2*s][0], el[2*s][1], el[2*s+1][0], el[2*s+1][1]};
                unsigned bh0 = vbh[s*8], bh1 = vbh[s*8 + 4];
                unsigned bl0 = vbl[s*8], bl1 = vbl[s*8 + 4];
                mma_bf16(po[nt6], a_h, bh0, bh1);
                mma_bf16(po[nt6], a_l, bh0, bh1);
                mma_bf16(po[nt6], a_h, bl0, bl1);
            }
            {   // leftover k8 (keys 64..71)
                unsigned bh0 = vbh[32], bl0 = vbl[32];
                mma_bf16_k8(po[nt6], eh[8], bh0);
                mma_bf16_k8(po[nt6], el[8], bh0);
                mma_bf16_k8(po[nt6], eh[8], bl0);
            }
        }
        // ---- store partials into buf (K region; all K reads done since S2) ----
        #pragma unroll
        for (int nt6 = 0; nt6 < 4; nt6++)
            *(float4*)&buf[(((ws*4 + nt6)*8 + wk)*32 + lane)*4] =
                make_float4(po[nt6][0], po[nt6][1], po[nt6][2], po[nt6][3]);
        __syncthreads();                        // S6
        // ---- reduce 8 key-slices; scale; write split bf16 O ----
        if (w < 8) {
            int rws = w >> 2, rnt = w & 3;
            float4 s4 = make_float4(0.f, 0.f, 0.f, 0.f);
            #pragma unroll
            for (int k = 0; k < 8; k++) {
                float4 p = *(const float4*)&buf[(((rws*4 + rnt)*8 + k)*32 + lane)*4];
                s4.x += p.x; s4.y += p.y; s4.z += p.z; s4.w += p.w;
            }
            int q0 = rws*16 + r4;
            int dh = rnt*8 + c4*2;
            float ri0 = rinv[q0], ri1 = rinv[q0 + 8];
            float x0 = s4.x*ri0, x1 = s4.y*ri0;
            float x2 = s4.z*ri1, x3 = s4.w*ri1;
            long orow = (long)(nb*SEQ + qt*32 + q0)*DIM + h*32 + dh;
            __nv_bfloat162 h0, l0, h1, l1;
            splitbf(x0, h0.x, l0.x); splitbf(x1, h0.y, l0.y);
            splitbf(x2, h1.x, l1.x); splitbf(x3, h1.y, l1.y);
            *(__nv_bfloat162*)&g_oh[orow]         = h0;
            *(__nv_bfloat162*)&g_ol[orow]         = l0;
            *(__nv_bfloat162*)&g_oh[orow + 8*DIM] = h1;
            *(__nv_bfloat162*)&g_ol[orow + 8*DIM] = l1;
        }
        __syncthreads();                        // S7: buf reads done before next P1
    }
    // ---- final: head-mean attention from registers ----
    float* aout = attn_out + (long)(layer*NB + nb)*SEQ*SEQ + (long)qt*32*SEQ;
    #pragma unroll
    for (int nt = 0; nt < 9; nt++) {
        int col = wk*72 + nt*8 + c4*2;
        *(float2*)&aout[(long)(ws*16 + r4)*SEQ + col]     = make_float2(am[nt][0], am[nt][1]);
        *(float2*)&aout[(long)(ws*16 + 8 + r4)*SEQ + col] = make_float2(am[nt][2], am[nt][3]);
    }
}

// ---------------- feature mean over sequence ----------------
__global__ void feat_k(void) {
    int ni = blockIdx.x, b = blockIdx.y, d = threadIdx.x;
    const float* p = g_pe + ((long)(ni*BATCH + b)*SEQ)*DIM + d;
    float s = 0.f;
    for (int t = 0; t < SEQ; t++) s += p[(long)t*DIM];
    g_feat[b*(NIMG*DIM) + ni*DIM + d] = s * (1.0f/576.0f);
}

// ---------------- MLP head ----------------
__global__ void head_k(const float* __restrict__ w1, const float* __restrict__ b1,
                       const float* __restrict__ w2, const float* __restrict__ b2,
                       float* __restrict__ out) {
    __shared__ float fs[NIMG*DIM];
    __shared__ float hs[MLPDIM];
    int b = blockIdx.x, tid = threadIdx.x;
    for (int t = tid; t < NIMG*DIM; t += MLPDIM) fs[t] = g_feat[b*NIMG*DIM + t];
    __syncthreads();
    float a = b1[tid];
    const float* wr = w1 + (long)tid*(NIMG*DIM);
    for (int d2 = 0; d2 < NIMG*DIM; d2++) a += fs[d2]*wr[d2];
    hs[tid] = fmaxf(a, 0.f) * w2[tid];
    __syncthreads();
    for (int st = 256; st > 0; st >>= 1) {
        if (tid < st) hs[tid] += hs[tid + st];
        __syncthreads();
    }
    if (tid == 0) out[b] = hs[0] + b2[0];
}

// ---------------- launch ----------------
extern "C" void kernel_launch(void* const* d_in, const int* in_sizes, int n_in,
                              void* d_out, int out_size) {
    const float* x      = (const float*)d_in[0];
    const float* conv_w = (const float*)d_in[1];
    const float* conv_b = (const float*)d_in[2];
    const float* pos_e  = (const float*)d_in[3];
    const float* in_w   = (const float*)d_in[4];
    const float* in_b   = (const float*)d_in[5];
    const float* out_w  = (const float*)d_in[6];
    const float* out_b  = (const float*)d_in[7];
    const float* hw1    = (const float*)d_in[8];
    const float* hb1    = (const float*)d_in[9];
    const float* hw2    = (const float*)d_in[10];
    const float* hb2    = (const float*)d_in[11];

    float* out  = (float*)d_out;            // [8]
    float* attn = out + BATCH;              // [6,4,8,576,576]

    cudaFuncSetAttribute(attn_mma, cudaFuncAttributeMaxDynamicSharedMemorySize, ATTN_SMEM);

    __nv_bfloat16 *imh_p, *iml_p, *peh_p, *pel_p, *oh_p, *ol_p;
    __nv_bfloat16 *cwh_p, *cwl_p, *iwh_p, *iwl_p, *owh_p, *owl_p;
    float *qkv_p, *pe_p;
    cudaGetSymbolAddress((void**)&imh_p, g_imh);
    cudaGetSymbolAddress((void**)&iml_p, g_iml);
    cudaGetSymbolAddress((void**)&peh_p, g_peh);
    cudaGetSymbolAddress((void**)&pel_p, g_pel);
    cudaGetSymbolAddress((void**)&oh_p,  g_oh);
    cudaGetSymbolAddress((void**)&ol_p,  g_ol);
    cudaGetSymbolAddress((void**)&cwh_p, g_cwh);
    cudaGetSymbolAddress((void**)&cwl_p, g_cwl);
    cudaGetSymbolAddress((void**)&iwh_p, g_iwh);
    cudaGetSymbolAddress((void**)&iwl_p, g_iwl);
    cudaGetSymbolAddress((void**)&owh_p, g_owh);
    cudaGetSymbolAddress((void**)&owl_p, g_owl);
    cudaGetSymbolAddress((void**)&qkv_p, g_qkv);
    cudaGetSymbolAddress((void**)&pe_p,  g_pe);

    // 0) weight splits
    cvt_bf<<<(NIMG*DIM*KPATCH + 255)/256, 256>>>(conv_w, cwh_p, cwl_p, NIMG*DIM*KPATCH);
    cvt_bf<<<(NLAYER*3*DIM*DIM + 255)/256, 256>>>(in_w, iwh_p, iwl_p, NLAYER*3*DIM*DIM);
    cvt_bf<<<(NLAYER*DIM*DIM + 255)/256, 256>>>(out_w, owh_p, owl_p, NLAYER*DIM*DIM);

    // 1) im2col (split)
    {
        long total = (long)NIMG*BATCH*SEQ*KPATCH;
        im2col_k<<<(int)((total + 255)/256), 256>>>(x);
    }
    // 2) patch-embed GEMM per image (+conv_b +pos) -> peh/pel
    {
        dim3 g(DIM/64, (BATCH*SEQ)/64, NIMG);
        gemm_bf3<<<g, 256>>>(imh_p, iml_p, cwh_p, cwl_p,
                             nullptr, peh_p, pel_p,
                             BATCH*SEQ, DIM, KPATCH,
                             conv_b, pos_e,
                             (long)BATCH*SEQ*KPATCH, (long)DIM*KPATCH,
                             (long)BATCH*SEQ*DIM, DIM);
    }
    // 3) transformer layers
    for (int l = 0; l < NLAYER; l++) {
        {   // qkv: (peh,pel) x in_w -> f32 qkv
            dim3 g((3*DIM)/64, TOK/64, 1);
            gemm_bf3<<<g, 256>>>(peh_p, pel_p,
                                 iwh_p + (long)l*3*DIM*DIM, iwl_p + (long)l*3*DIM*DIM,
                                 qkv_p, nullptr, nullptr,
                                 TOK, 3*DIM, DIM,
                                 in_b + (long)l*3*DIM, nullptr, 0, 0, 0, 0);
        }
        {
            dim3 g(SEQ/32, NB, 1);
            attn_mma<<<g, 512, ATTN_SMEM>>>(qkv_p, attn, l);
        }
        {   // out-proj: (oh,ol) x out_w -> pe f32 + peh/pel
            dim3 g(DIM/64, TOK/64, 1);
            gemm_bf3<<<g, 256>>>(oh_p, ol_p,
                                 owh_p + (long)l*DIM*DIM, owl_p + (long)l*DIM*DIM,
                                 pe_p, peh_p, pel_p,
                                 TOK, DIM, DIM,
                                 out_b + (long)l*DIM, nullptr, 0, 0, 0, 0);
        }
    }
    // 4) sequence-mean features + MLP head
    {
        dim3 g(NIMG, BATCH);
        feat_k<<<g, DIM>>>();
    }
    head_k<<<BATCH, MLPDIM>>>(hw1, hb1, hw2, hb2, out);
}